// round 13
// baseline (speedup 1.0000x reference)
#include <cuda_runtime.h>
#include <cuda_fp16.h>
#include <cstdint>

#define NT 256                 // 8 warps: 4 (m) x 2 (n), warp tile 32x64
#define BM 128
#define KP 16                  // k-pair words per tile (BK=32 k)
#define MSTRIDE 136            // u32 stride for A smem [kp][m]
#define WS_STRIDE 136          // u32 stride for W smem [kp][n]
#define A_TILE (KP * MSTRIDE)  // 2176 u32
#define W_TILE (KP * WS_STRIDE)
#define OFF_W  (2 * A_TILE)
#define OFF_BIAS (2 * A_TILE + 2 * W_TILE)
#define SMEM_BYTES ((2 * A_TILE + 2 * W_TILE + 128) * 4)   // 35328 B

#define MAXS 150016

// Pre-scaled fp16x2-packed weights, [job][kp][n=128] u32
__device__ uint32_t g_wt[147456];
// Pre-gated fp16x2-packed A features: concatenated [g][S] for g in [0,960):
//   g 0..191   : region0 features (K=384)
//   g 192..447 : region1 (K=512), 448..703: region2, 704..959: region3
__device__ uint32_t g_af[960ull * MAXS];

__device__ __forceinline__ uint32_t smem_u32(const void* p) {
    uint32_t a;
    asm("{ .reg .u64 t; cvta.to.shared.u64 t, %1; cvt.u32.u64 %0, t; }" : "=r"(a) : "l"(p));
    return a;
}
__device__ __forceinline__ void cp16(uint32_t dst, const void* src) {
    asm volatile("cp.async.ca.shared.global [%0], [%1], 16;" :: "r"(dst), "l"(src));
}
__device__ __forceinline__ uint32_t pack_h2(float lo, float hi) {
    half2 h = __floats2half2_rn(lo, hi);
    return *(uint32_t*)&h;
}
__device__ __forceinline__ void mma_f16(float* d, const uint32_t* a, const uint32_t* b) {
    asm volatile(
        "mma.sync.aligned.m16n8k16.row.col.f32.f16.f16.f32 "
        "{%0,%1,%2,%3}, {%4,%5,%6,%7}, {%8,%9}, {%0,%1,%2,%3};"
        : "+f"(d[0]), "+f"(d[1]), "+f"(d[2]), "+f"(d[3])
        : "r"(a[0]), "r"(a[1]), "r"(a[2]), "r"(a[3]), "r"(b[0]), "r"(b[1]));
}

// ---------------- prep: fold scales + fp16 pack weights ----------------
__global__ void prep_wt(const float* __restrict__ w000, const float* __restrict__ w110,
                        const float* __restrict__ w011, const float* __restrict__ w101,
                        const float* __restrict__ w111)
{
    const float SQK0 = 0.05103103630798288f;
    const float SQK1 = 0.04419417382415922f;
    const float IS3  = 0.57735026918962584f;
    const float IS2  = 0.70710678118654752f;

    int idx = blockIdx.x * 256 + threadIdx.x;
    if (idx >= 147456) return;
    int job, rem;
    if (idx < 49152) { job = idx / 24576; rem = idx % 24576; }
    else             { int t = idx - 49152; job = 2 + t / 32768; rem = t % 32768; }
    int kp = rem >> 7, n = rem & 127;

    float w2[2];
    #pragma unroll
    for (int h = 0; h < 2; h++) {
        int k = 2 * kp + h;
        float v;
        if (job < 2) {
            int cb = job;
            if (k < 256) v = SQK0 * w000[k * 256 + cb * 128 + n];
            else         v = SQK0 * IS3 * w110[(k - 256) * 256 + cb * 128 + n];
        } else {
            if (k < 256)      v = SQK1 * w011[k * 128 + n];
            else if (k < 384) v = SQK1 * w101[(k - 256) * 128 + n];
            else              v = SQK1 * IS2 * w111[(k - 384) * 128 + n];
        }
        w2[h] = v;
    }
    g_wt[idx] = pack_h2(w2[0], w2[1]);
}

// ---------------- prep: compute all gated A features, fp16 packed ----------------
// 32 rows per CTA; x tile transposed in smem; writes fully coalesced (lane = row).
__global__ void __launch_bounds__(256, 1)
prep_feat(const float* __restrict__ x, const float* __restrict__ y, int B, int S)
{
    extern __shared__ float sxt[];         // [640][33]: sxt[c*33 + r]
    const int tid  = threadIdx.x;
    const int wid  = tid >> 5;
    const int lane = tid & 31;
    const int r0   = blockIdx.x * 32;

    #pragma unroll
    for (int i = 0; i < 80; i++) {
        int idx = tid + i * 256;           // over 32*640
        int r = idx / 640, c = idx % 640;
        float v = (r0 + r < B) ? x[(size_t)(r0 + r) * 640 + c] : 0.0f;
        sxt[c * 33 + r] = v;
    }
    __syncthreads();

    const int r = r0 + lane;
    float yv[4] = {0.f, 0.f, 0.f, 0.f};
    if (r < B) {
        float4 t = *(const float4*)(y + (size_t)r * 4);
        yv[0] = t.x; yv[1] = t.y; yv[2] = t.z; yv[3] = t.w;
    }

    for (int g = wid; g < 960; g += 8) {
        int f, kp;
        if (g < 192)      { f = 0; kp = g; }
        else if (g < 448) { f = 1; kp = g - 192; }
        else if (g < 704) { f = 2; kp = g - 448; }
        else              { f = 3; kp = g - 704; }
        const int i0 = f - 1;
        const int j1 = (i0 + 1) % 3;
        const int j2 = (i0 + 2) % 3;

        float fv[2];
        #pragma unroll
        for (int h = 0; h < 2; h++) {
            int k = 2 * kp + h;
            float v;
            if (k < 256) {
                float s = (f == 0) ? yv[0] : yv[1 + i0];
                v = sxt[k * 33 + lane] * s;
            } else if (f == 0) {
                int c = 256 + 3 * (k - 256);
                v = sxt[c * 33 + lane]       * yv[1]
                  + sxt[(c + 1) * 33 + lane] * yv[2]
                  + sxt[(c + 2) * 33 + lane] * yv[3];
            } else if (k < 384) {
                v = sxt[(256 + 3 * (k - 256) + i0) * 33 + lane] * yv[0];
            } else {
                int c = 256 + 3 * (k - 384);
                v = sxt[(c + j1) * 33 + lane] * yv[1 + j2]
                  - sxt[(c + j2) * 33 + lane] * yv[1 + j1];
            }
            fv[h] = v;
        }
        g_af[(size_t)g * S + r] = pack_h2(fv[0], fv[1]);
    }
}

// ---------------- main kernel: pure cp.async staging + MMA ----------------
__global__ void __launch_bounds__(NT, 2)
tpr_kernel(const float* __restrict__ b0, float* __restrict__ out, int B, int S)
{
    extern __shared__ uint32_t sm[];
    const uint32_t sb = smem_u32(sm);

    const int job  = blockIdx.x;
    const int row0 = blockIdx.y * BM;
    const int tid  = threadIdx.x;
    const int wid  = tid >> 5;
    const int lane = tid & 31;
    const int qr   = lane >> 2;
    const int qc   = lane & 3;
    const int wm   = wid & 3;     // warp m (32 rows)
    const int wn   = wid >> 2;    // warp n (64 cols)

    int region, cb;
    if (job < 2) { region = 0; cb = job; } else { region = job - 1; cb = 0; }
    const int i0 = region - 1;
    const int KT = (region == 0) ? 12 : 16;
    const uint32_t* wbase  = g_wt + ((job < 2) ? job * 24576 : 49152 + (job - 2) * 32768);
    const int fstart = (region == 0) ? 0 : 192 + (region - 1) * 256;
    const uint32_t* afbase = g_af + (size_t)fstart * S + row0;

    if (region == 0 && tid < 128)
        ((float*)(sm + OFF_BIAS))[tid] = b0[cb * 128 + tid];

    float acc[2][8][4];
    #pragma unroll
    for (int mi = 0; mi < 2; mi++)
        #pragma unroll
        for (int ni = 0; ni < 8; ni++)
            #pragma unroll
            for (int c = 0; c < 4; c++) acc[mi][ni][c] = 0.f;

    // ---- stage A + W tiles: pure cp.async ----
    auto issueTiles = [&](int kt, int b) {
        // A: 16 kp x 128 m u32 -> [kp][m] stride MSTRIDE
        {
            const uint32_t dbase = sb + (b * A_TILE) * 4;
            const uint32_t* src = afbase + (size_t)(kt * KP) * S;
            #pragma unroll
            for (int i = 0; i < 2; i++) {
                int idx = tid + i * NT;          // 512 chunks
                int kw = idx >> 5, m16 = (idx & 31) * 4;
                cp16(dbase + (uint32_t)(kw * MSTRIDE + m16) * 4,
                     src + (size_t)kw * S + m16);
            }
        }
        // W: 16 kp x 128 n u32 -> [kp][n] stride WS_STRIDE
        {
            const uint32_t dbase = sb + (OFF_W + b * W_TILE) * 4;
            const uint32_t* src = wbase + (size_t)(kt * KP) * 128;
            #pragma unroll
            for (int i = 0; i < 2; i++) {
                int idx = tid + i * NT;
                int kw = idx >> 5, c16 = (idx & 31) * 4;
                cp16(dbase + (uint32_t)(kw * WS_STRIDE + c16) * 4,
                     src + kw * 128 + c16);
            }
        }
        asm volatile("cp.async.commit_group;" ::: "memory");
    };

    // ---------- prologue ----------
    issueTiles(0, 0);

    // ---------- main loop ----------
    for (int kt = 0; kt < KT; kt++) {
        const int b = kt & 1;
        asm volatile("cp.async.wait_group 0;" ::: "memory");
        __syncthreads();

        if (kt + 1 < KT) issueTiles(kt + 1, b ^ 1);

        const uint32_t* Ab = sm + b * A_TILE;
        const uint32_t* Wb = sm + OFF_W + b * W_TILE;
        #pragma unroll
        for (int ks = 0; ks < 2; ks++) {
            const int base = ks * 8;           // k-pair base (k16 per MMA)
            uint32_t a[2][4];
            #pragma unroll
            for (int mi = 0; mi < 2; mi++) {
                const uint32_t* p = &Ab[(base + qc) * MSTRIDE + wm * 32 + mi * 16 + qr];
                a[mi][0] = p[0];
                a[mi][1] = p[8];
                a[mi][2] = p[4 * MSTRIDE];
                a[mi][3] = p[4 * MSTRIDE + 8];
            }
            #pragma unroll
            for (int ni = 0; ni < 8; ni++) {
                uint32_t bb[2];
                const uint32_t* q = &Wb[(base + qc) * WS_STRIDE + wn * 64 + ni * 8 + qr];
                bb[0] = q[0];
                bb[1] = q[4 * WS_STRIDE];
                mma_f16(acc[0][ni], a[0], bb);
                mma_f16(acc[1][ni], a[1], bb);
            }
        }
    }

    // ---------- epilogue ----------
    const float* bias = (const float*)(sm + OFF_BIAS);
    #pragma unroll
    for (int mi = 0; mi < 2; mi++) {
        #pragma unroll
        for (int half = 0; half < 2; half++) {
            int row = row0 + wm * 32 + mi * 16 + qr + half * 8;
            if (row >= B) continue;
            if (region == 0) {
                float* o = out + (size_t)row * 640 + cb * 128;
                #pragma unroll
                for (int ni = 0; ni < 8; ni++) {
                    int col = wn * 64 + ni * 8 + qc * 2;
                    float2 v = make_float2(acc[mi][ni][half * 2]     + bias[col],
                                           acc[mi][ni][half * 2 + 1] + bias[col + 1]);
                    *(float2*)(o + col) = v;
                }
            } else {
                float* o = out + (size_t)row * 640 + 256 + i0;
                #pragma unroll
                for (int ni = 0; ni < 8; ni++) {
                    int col = wn * 64 + ni * 8 + qc * 2;
                    o[col * 3]       = acc[mi][ni][half * 2];
                    o[(col + 1) * 3] = acc[mi][ni][half * 2 + 1];
                }
            }
        }
    }
}

extern "C" void kernel_launch(void* const* d_in, const int* in_sizes, int n_in,
                              void* d_out, int out_size)
{
    const float* x    = (const float*)d_in[0];
    const float* y    = (const float*)d_in[1];
    const float* w000 = (const float*)d_in[2];
    const float* w110 = (const float*)d_in[3];
    const float* w011 = (const float*)d_in[4];
    const float* w101 = (const float*)d_in[5];
    const float* w111 = (const float*)d_in[6];
    const float* b0   = (const float*)d_in[7];
    int B = in_sizes[0] / 640;
    int S = (B + 127) & ~127;
    if (S > MAXS) S = MAXS;

    const int PF_SMEM = 640 * 33 * 4;   // 84480 B
    cudaFuncSetAttribute(prep_feat, cudaFuncAttributeMaxDynamicSharedMemorySize, PF_SMEM);
    cudaFuncSetAttribute(tpr_kernel, cudaFuncAttributeMaxDynamicSharedMemorySize, SMEM_BYTES);

    prep_wt<<<(147456 + 255) / 256, 256>>>(w000, w110, w011, w101, w111);
    prep_feat<<<S / 32, 256, PF_SMEM>>>(x, y, B, S);

    dim3 grid(5, (B + BM - 1) / BM);
    tpr_kernel<<<grid, NT, SMEM_BYTES>>>(b0, (float*)d_out, B, S);
}

// round 14
// speedup vs baseline: 1.5833x; 1.5833x over previous
#include <cuda_runtime.h>
#include <cuda_fp16.h>
#include <cstdint>

#define NT 256                 // 8 warps: 4 (m) x 2 (n), warp tile 32x64
#define BM 128
#define BK 64                  // K floats per tile -> 32 half2 words
#define KP 32                  // k-pair words per tile
#define AS_STRIDE 36           // u32 stride [m][kp]: frag banks 4*qr+qc distinct
#define WS_STRIDE 136          // u32 stride [kp][n]: frag banks 8*qc+qr distinct
#define A_TILE (BM * AS_STRIDE)        // 4608 u32
#define W_TILE (KP * WS_STRIDE)        // 4352 u32
#define OFF_W  (2 * A_TILE)
#define OFF_BIAS (2 * A_TILE + 2 * W_TILE)
#define SMEM_BYTES ((2 * A_TILE + 2 * W_TILE + 128) * 4)   // 72192 B

#define MAXS 150016            // max padded row count for g_xt

// Pre-scaled fp16x2-packed weights, [job][kp][n=128] u32
__device__ uint32_t g_wt[147456];
// Transposed x: g_xt[c * S + r], c in [0,640)
__device__ float g_xt[640ull * MAXS];

__device__ __forceinline__ uint32_t smem_u32(const void* p) {
    uint32_t a;
    asm("{ .reg .u64 t; cvta.to.shared.u64 t, %1; cvt.u32.u64 %0, t; }" : "=r"(a) : "l"(p));
    return a;
}
__device__ __forceinline__ void cp16(uint32_t dst, const void* src) {
    asm volatile("cp.async.ca.shared.global [%0], [%1], 16;" :: "r"(dst), "l"(src));
}
__device__ __forceinline__ uint32_t pack_h2(float lo, float hi) {
    half2 h = __floats2half2_rn(lo, hi);
    return *(uint32_t*)&h;
}
__device__ __forceinline__ void mma_f16(float* d, const uint32_t* a, const uint32_t* b) {
    asm volatile(
        "mma.sync.aligned.m16n8k16.row.col.f32.f16.f16.f32 "
        "{%0,%1,%2,%3}, {%4,%5,%6,%7}, {%8,%9}, {%0,%1,%2,%3};"
        : "+f"(d[0]), "+f"(d[1]), "+f"(d[2]), "+f"(d[3])
        : "r"(a[0]), "r"(a[1]), "r"(a[2]), "r"(a[3]), "r"(b[0]), "r"(b[1]));
}

// ---------------- prep: transpose x -> g_xt ----------------
__global__ void prep_xt(const float* __restrict__ x, int B, int S)
{
    __shared__ float t[32][33];
    const int tx = threadIdx.x, ty = threadIdx.y;
    const int c0 = blockIdx.x * 32;
    const int r0 = blockIdx.y * 32;
    #pragma unroll
    for (int i = 0; i < 4; i++) {
        int r = r0 + ty + i * 8;
        t[ty + i * 8][tx] = (r < B) ? x[(size_t)r * 640 + c0 + tx] : 0.0f;
    }
    __syncthreads();
    #pragma unroll
    for (int i = 0; i < 4; i++) {
        int c = c0 + ty + i * 8;
        g_xt[(size_t)c * S + r0 + tx] = t[tx][ty + i * 8];
    }
}

// ---------------- prep: fold scales + fp16 pack (k-pairs) ----------------
__global__ void prep_wt(const float* __restrict__ w000, const float* __restrict__ w110,
                        const float* __restrict__ w011, const float* __restrict__ w101,
                        const float* __restrict__ w111)
{
    const float SQK0 = 0.05103103630798288f;
    const float SQK1 = 0.04419417382415922f;
    const float IS3  = 0.57735026918962584f;
    const float IS2  = 0.70710678118654752f;

    int idx = blockIdx.x * 256 + threadIdx.x;
    if (idx >= 147456) return;
    int job, rem;
    if (idx < 49152) { job = idx / 24576; rem = idx % 24576; }
    else             { int t = idx - 49152; job = 2 + t / 32768; rem = t % 32768; }
    int kp = rem >> 7, n = rem & 127;

    float w2[2];
    #pragma unroll
    for (int h = 0; h < 2; h++) {
        int k = 2 * kp + h;
        float v;
        if (job < 2) {
            int cb = job;
            if (k < 256) v = SQK0 * w000[k * 256 + cb * 128 + n];
            else         v = SQK0 * IS3 * w110[(k - 256) * 256 + cb * 128 + n];
        } else {
            if (k < 256)      v = SQK1 * w011[k * 128 + n];
            else if (k < 384) v = SQK1 * w101[(k - 256) * 128 + n];
            else              v = SQK1 * IS2 * w111[(k - 384) * 128 + n];
        }
        w2[h] = v;
    }
    g_wt[idx] = pack_h2(w2[0], w2[1]);
}

// ---------------- main kernel ----------------
__global__ void __launch_bounds__(NT, 2)
tpr_kernel(const float* __restrict__ y, const float* __restrict__ b0,
           float* __restrict__ out, int B, int S)
{
    extern __shared__ uint32_t sm[];
    const uint32_t sb = smem_u32(sm);

    const int job  = blockIdx.x;
    const int row0 = blockIdx.y * BM;
    const int tid  = threadIdx.x;
    const int wid  = tid >> 5;
    const int lane = tid & 31;
    const int qr   = lane >> 2;
    const int qc   = lane & 3;
    const int wm   = wid & 3;     // warp m (32 rows)
    const int wn   = wid >> 2;    // warp n (64 cols)

    int region, cb;
    if (job < 2) { region = 0; cb = job; } else { region = job - 1; cb = 0; }
    const int i0 = region - 1;
    const int j1 = (i0 + 1) % 3;
    const int j2 = (i0 + 2) % 3;
    const int KT = (region == 0) ? 6 : 8;          // K/64 tiles
    const uint32_t* wbase = g_wt + ((job < 2) ? job * 24576 : 49152 + (job - 2) * 32768);

    // staging role: one row per thread-pair, 16 k per pass (2 passes per tile)
    const int fm   = tid >> 1;
    const int klo  = (tid & 1) * 16;       // k offset within a 32-k half
    const int kwo  = (tid & 1) * 8;        // word offset within a 16-kp half
    const int frow = row0 + fm;
    const bool valid = frow < B;
    float yv[4] = {0.f, 0.f, 0.f, 0.f};
    if (valid) {
        float4 t = *(const float4*)(y + (size_t)frow * 4);
        yv[0] = t.x; yv[1] = t.y; yv[2] = t.z; yv[3] = t.w;
    }
    if (region == 0 && tid < 128)
        ((float*)(sm + OFF_BIAS))[tid] = b0[cb * 128 + tid];

    float acc[2][8][4];
    #pragma unroll
    for (int mi = 0; mi < 2; mi++)
        #pragma unroll
        for (int ni = 0; ni < 8; ni++)
            #pragma unroll
            for (int c = 0; c < 4; c++) acc[mi][ni][c] = 0.f;

    // ---- W tile: cp.async straight copy (pre-packed fp16x2), 32 kp ----
    auto issueW = [&](int kt, int b) {
        const uint32_t dbase = sb + (OFF_W + b * W_TILE) * 4;
        const uint32_t* src = wbase + (size_t)(kt * KP) * 128;
        #pragma unroll
        for (int i = 0; i < 4; i++) {
            int idx = tid + i * NT;            // 1024 chunks of 16B
            int kw = idx >> 5, c16 = (idx & 31) * 4;
            cp16(dbase + (uint32_t)(kw * WS_STRIDE + c16) * 4,
                 src + kw * 128 + c16);
        }
        asm volatile("cp.async.commit_group;" ::: "memory");
    };

    // ---- A features: 16 gated values at absolute k offset kg0 ----
    auto load_feat = [&](int kg0, float* f) {
        if (!valid) {
            #pragma unroll
            for (int j = 0; j < 16; j++) f[j] = 0.f;
        } else if (kg0 < 256) {
            float s = (region == 0) ? yv[0] : yv[1 + i0];
            const float* cp = g_xt + (size_t)kg0 * S + frow;
            #pragma unroll
            for (int j = 0; j < 16; j++)
                f[j] = cp[(size_t)j * S] * s;
        } else {
            int u0, mode;
            if (region == 0)    { u0 = kg0 - 256; mode = 0; }
            else if (kg0 < 384) { u0 = kg0 - 256; mode = 1; }
            else                { u0 = kg0 - 384; mode = 2; }
            const float* bp = g_xt + (size_t)(256 + 3 * u0) * S + frow;
            if (mode == 0) {
                #pragma unroll
                for (int j = 0; j < 16; j++) {
                    float e0 = bp[(size_t)(3*j)   * S];
                    float e1 = bp[(size_t)(3*j+1) * S];
                    float e2 = bp[(size_t)(3*j+2) * S];
                    f[j] = e0 * yv[1] + e1 * yv[2] + e2 * yv[3];
                }
            } else if (mode == 1) {
                #pragma unroll
                for (int j = 0; j < 16; j++)
                    f[j] = bp[(size_t)(3*j + i0) * S] * yv[0];
            } else {
                #pragma unroll
                for (int j = 0; j < 16; j++) {
                    float xa = bp[(size_t)(3*j + j1) * S];
                    float xb = bp[(size_t)(3*j + j2) * S];
                    f[j] = xa * yv[1 + j2] - xb * yv[1 + j1];
                }
            }
        }
    };
    auto storeA = [&](int b, int half, const float* f) {
        uint32_t* ap = sm + b * A_TILE + fm * AS_STRIDE + half * 16 + kwo;
        uint4 u0 = make_uint4(pack_h2(f[0], f[1]),   pack_h2(f[2], f[3]),
                              pack_h2(f[4], f[5]),   pack_h2(f[6], f[7]));
        uint4 u1 = make_uint4(pack_h2(f[8], f[9]),   pack_h2(f[10], f[11]),
                              pack_h2(f[12], f[13]), pack_h2(f[14], f[15]));
        *(uint4*)(ap)     = u0;
        *(uint4*)(ap + 4) = u1;
    };

    // ---------- prologue: stage tile 0 ----------
    float f[16];
    issueW(0, 0);
    load_feat(klo, f);          storeA(0, 0, f);
    load_feat(32 + klo, f);     storeA(0, 1, f);

    // ---------- main loop: 1 barrier per 64-k tile ----------
    for (int kt = 0; kt < KT; kt++) {
        const int b = kt & 1;
        asm volatile("cp.async.wait_group 0;" ::: "memory");
        __syncthreads();

        const bool more = (kt + 1 < KT);
        if (more) { issueW(kt + 1, b ^ 1); load_feat((kt + 1) * BK + klo, f); }

        const uint32_t* Ab = sm + b * A_TILE;
        const uint32_t* Wb = sm + OFF_W + b * W_TILE;

        // first half: ks 0,1
        #pragma unroll
        for (int ks = 0; ks < 2; ks++) {
            const int base = ks * 8;
            uint32_t a[2][4];
            #pragma unroll
            for (int mi = 0; mi < 2; mi++) {
                const uint32_t* p = &Ab[(wm * 32 + mi * 16 + qr) * AS_STRIDE + base + qc];
                a[mi][0] = p[0];
                a[mi][1] = p[8 * AS_STRIDE];
                a[mi][2] = p[4];
                a[mi][3] = p[8 * AS_STRIDE + 4];
            }
            #pragma unroll
            for (int ni = 0; ni < 8; ni++) {
                uint32_t bb[2];
                const uint32_t* q = &Wb[(base + qc) * WS_STRIDE + wn * 64 + ni * 8 + qr];
                bb[0] = q[0];
                bb[1] = q[4 * WS_STRIDE];
                mma_f16(acc[0][ni], a[0], bb);
                mma_f16(acc[1][ni], a[1], bb);
            }
        }

        if (more) { storeA(b ^ 1, 0, f); load_feat((kt + 1) * BK + 32 + klo, f); }

        // second half: ks 2,3
        #pragma unroll
        for (int ks = 2; ks < 4; ks++) {
            const int base = ks * 8;
            uint32_t a[2][4];
            #pragma unroll
            for (int mi = 0; mi < 2; mi++) {
                const uint32_t* p = &Ab[(wm * 32 + mi * 16 + qr) * AS_STRIDE + base + qc];
                a[mi][0] = p[0];
                a[mi][1] = p[8 * AS_STRIDE];
                a[mi][2] = p[4];
                a[mi][3] = p[8 * AS_STRIDE + 4];
            }
            #pragma unroll
            for (int ni = 0; ni < 8; ni++) {
                uint32_t bb[2];
                const uint32_t* q = &Wb[(base + qc) * WS_STRIDE + wn * 64 + ni * 8 + qr];
                bb[0] = q[0];
                bb[1] = q[4 * WS_STRIDE];
                mma_f16(acc[0][ni], a[0], bb);
                mma_f16(acc[1][ni], a[1], bb);
            }
        }

        if (more) storeA(b ^ 1, 1, f);
    }

    // ---------- epilogue ----------
    const float* bias = (const float*)(sm + OFF_BIAS);
    #pragma unroll
    for (int mi = 0; mi < 2; mi++) {
        #pragma unroll
        for (int half = 0; half < 2; half++) {
            int row = row0 + wm * 32 + mi * 16 + qr + half * 8;
            if (row >= B) continue;
            if (region == 0) {
                float* o = out + (size_t)row * 640 + cb * 128;
                #pragma unroll
                for (int ni = 0; ni < 8; ni++) {
                    int col = wn * 64 + ni * 8 + qc * 2;
                    float2 v = make_float2(acc[mi][ni][half * 2]     + bias[col],
                                           acc[mi][ni][half * 2 + 1] + bias[col + 1]);
                    *(float2*)(o + col) = v;
                }
            } else {
                float* o = out + (size_t)row * 640 + 256 + i0;
                #pragma unroll
                for (int ni = 0; ni < 8; ni++) {
                    int col = wn * 64 + ni * 8 + qc * 2;
                    o[col * 3]       = acc[mi][ni][half * 2];
                    o[(col + 1) * 3] = acc[mi][ni][half * 2 + 1];
                }
            }
        }
    }
}

extern "C" void kernel_launch(void* const* d_in, const int* in_sizes, int n_in,
                              void* d_out, int out_size)
{
    const float* x    = (const float*)d_in[0];
    const float* y    = (const float*)d_in[1];
    const float* w000 = (const float*)d_in[2];
    const float* w110 = (const float*)d_in[3];
    const float* w011 = (const float*)d_in[4];
    const float* w101 = (const float*)d_in[5];
    const float* w111 = (const float*)d_in[6];
    const float* b0   = (const float*)d_in[7];
    int B = in_sizes[0] / 640;
    int S = (B + 127) & ~127;
    if (S > MAXS) S = MAXS;

    cudaFuncSetAttribute(tpr_kernel, cudaFuncAttributeMaxDynamicSharedMemorySize,
                         SMEM_BYTES);

    prep_wt<<<(147456 + 255) / 256, 256>>>(w000, w110, w011, w101, w111);
    {
        dim3 tb(32, 8), tg(640 / 32, S / 32);
        prep_xt<<<tg, tb>>>(x, B, S);
    }

    dim3 grid(5, (B + BM - 1) / BM);
    tpr_kernel<<<grid, NT, SMEM_BYTES>>>(y, b0, (float*)d_out, B, S);
}

// round 15
// speedup vs baseline: 1.6973x; 1.0720x over previous
#include <cuda_runtime.h>
#include <cuda_fp16.h>
#include <cstdint>

#define NT 256                 // 8 warps: 4 (m) x 2 (n), warp tile 32x64
#define BM 128
#define BK 64                  // K floats per tile -> 32 half2 words
#define KP 32
#define AS_STRIDE 36           // u32 stride [m][kp]
#define WS_STRIDE 136          // u32 stride [kp][n]
#define A_TILE (BM * AS_STRIDE)
#define W_TILE (KP * WS_STRIDE)
#define OFF_W  (2 * A_TILE)
#define OFF_BIAS (2 * A_TILE + 2 * W_TILE)
#define SMEM_BYTES ((2 * A_TILE + 2 * W_TILE + 128) * 4)   // 72192 B

#define MAXS 150016

// weights (fp16x2, scales folded), u32 layout:
//  [0)      job0: out0 cb0, 192 kp x 128
//  [24576)  job1: out0 cb1, 192 kp x 128
//  [49152)  z011: SQK1*w011, 128 kp x 128
//  [65536)  regions: [SQK1*w101 ; SQK1*IS2*w111], 128 kp x 128
__device__ uint32_t g_wt[81920];
__device__ float g_xt[640ull * MAXS];      // x transposed: [c][S]
__device__ float g_z[(size_t)MAXS * 128];  // z011 scratch (SQK1 folded)

__device__ __forceinline__ uint32_t smem_u32(const void* p) {
    uint32_t a;
    asm("{ .reg .u64 t; cvta.to.shared.u64 t, %1; cvt.u32.u64 %0, t; }" : "=r"(a) : "l"(p));
    return a;
}
__device__ __forceinline__ void cp16(uint32_t dst, const void* src) {
    asm volatile("cp.async.ca.shared.global [%0], [%1], 16;" :: "r"(dst), "l"(src));
}
__device__ __forceinline__ uint32_t pack_h2(float lo, float hi) {
    half2 h = __floats2half2_rn(lo, hi);
    return *(uint32_t*)&h;
}
__device__ __forceinline__ void mma_f16(float* d, const uint32_t* a, const uint32_t* b) {
    asm volatile(
        "mma.sync.aligned.m16n8k16.row.col.f32.f16.f16.f32 "
        "{%0,%1,%2,%3}, {%4,%5,%6,%7}, {%8,%9}, {%0,%1,%2,%3};"
        : "+f"(d[0]), "+f"(d[1]), "+f"(d[2]), "+f"(d[3])
        : "r"(a[0]), "r"(a[1]), "r"(a[2]), "r"(a[3]), "r"(b[0]), "r"(b[1]));
}

// ---------------- prep: transpose x ----------------
__global__ void prep_xt(const float* __restrict__ x, int B, int S)
{
    __shared__ float t[32][33];
    const int tx = threadIdx.x, ty = threadIdx.y;
    const int c0 = blockIdx.x * 32;
    const int r0 = blockIdx.y * 32;
    #pragma unroll
    for (int i = 0; i < 4; i++) {
        int r = r0 + ty + i * 8;
        t[ty + i * 8][tx] = (r < B) ? x[(size_t)r * 640 + c0 + tx] : 0.0f;
    }
    __syncthreads();
    #pragma unroll
    for (int i = 0; i < 4; i++) {
        int c = c0 + ty + i * 8;
        g_xt[(size_t)c * S + r0 + tx] = t[tx][ty + i * 8];
    }
}

// ---------------- prep: fold scales + fp16 pack ----------------
__global__ void prep_wt(const float* __restrict__ w000, const float* __restrict__ w110,
                        const float* __restrict__ w011, const float* __restrict__ w101,
                        const float* __restrict__ w111)
{
    const float SQK0 = 0.05103103630798288f;
    const float SQK1 = 0.04419417382415922f;
    const float IS3  = 0.57735026918962584f;
    const float IS2  = 0.70710678118654752f;

    int idx = blockIdx.x * 256 + threadIdx.x;
    if (idx >= 81920) return;
    float w2[2];
    if (idx < 49152) {
        int job = idx / 24576, rem = idx % 24576;
        int kp = rem >> 7, n = rem & 127, cb = job;
        #pragma unroll
        for (int h = 0; h < 2; h++) {
            int k = 2 * kp + h;
            w2[h] = (k < 256) ? SQK0 * w000[k * 256 + cb * 128 + n]
                              : SQK0 * IS3 * w110[(k - 256) * 256 + cb * 128 + n];
        }
    } else if (idx < 65536) {
        int rem = idx - 49152;
        int kp = rem >> 7, n = rem & 127;
        #pragma unroll
        for (int h = 0; h < 2; h++)
            w2[h] = SQK1 * w011[(2 * kp + h) * 128 + n];
    } else {
        int rem = idx - 65536;
        int kp = rem >> 7, n = rem & 127;
        #pragma unroll
        for (int h = 0; h < 2; h++) {
            int k = 2 * kp + h;
            w2[h] = (k < 128) ? SQK1 * w101[k * 128 + n]
                              : SQK1 * IS2 * w111[(k - 128) * 128 + n];
        }
    }
    g_wt[idx] = pack_h2(w2[0], w2[1]);
}

// ================= phase A: out0 (jobs 0,1) + z011 (job 2) =================
__global__ void __launch_bounds__(NT, 2)
tpr_a(const float* __restrict__ y, const float* __restrict__ b0,
      float* __restrict__ out, int B, int S)
{
    extern __shared__ uint32_t sm[];
    const uint32_t sb = smem_u32(sm);

    const int job  = blockIdx.x;
    const int row0 = blockIdx.y * BM;
    const int tid  = threadIdx.x;
    const int wid  = tid >> 5;
    const int lane = tid & 31;
    const int qr = lane >> 2, qc = lane & 3;
    const int wm = wid & 3, wn = wid >> 2;

    const bool is_z = (job == 2);
    const int KT = is_z ? 4 : 6;
    const uint32_t* wbase = g_wt + (is_z ? 49152 : job * 24576);

    const int fm   = tid >> 1;
    const int klo  = (tid & 1) * 16;
    const int kwo  = (tid & 1) * 8;
    const int frow = row0 + fm;
    const bool valid = frow < B;
    float yv[4] = {0.f, 0.f, 0.f, 0.f};
    if (valid) {
        float4 t = *(const float4*)(y + (size_t)frow * 4);
        yv[0] = t.x; yv[1] = t.y; yv[2] = t.z; yv[3] = t.w;
    }
    if (!is_z && tid < 128)
        ((float*)(sm + OFF_BIAS))[tid] = b0[job * 128 + tid];

    float acc[2][8][4];
    #pragma unroll
    for (int mi = 0; mi < 2; mi++)
        #pragma unroll
        for (int ni = 0; ni < 8; ni++)
            #pragma unroll
            for (int c = 0; c < 4; c++) acc[mi][ni][c] = 0.f;

    auto issueW = [&](int kt, int b) {
        const uint32_t dbase = sb + (OFF_W + b * W_TILE) * 4;
        const uint32_t* src = wbase + (size_t)(kt * KP) * 128;
        #pragma unroll
        for (int i = 0; i < 4; i++) {
            int idx = tid + i * NT;
            int kw = idx >> 5, c16 = (idx & 31) * 4;
            cp16(dbase + (uint32_t)(kw * WS_STRIDE + c16) * 4, src + kw * 128 + c16);
        }
        asm volatile("cp.async.commit_group;" ::: "memory");
    };

    auto load_feat = [&](int kg0, float* f) {
        if (!valid) {
            #pragma unroll
            for (int j = 0; j < 16; j++) f[j] = 0.f;
        } else if (kg0 < 256) {
            float s = is_z ? 1.0f : yv[0];
            const float* cp = g_xt + (size_t)kg0 * S + frow;
            #pragma unroll
            for (int j = 0; j < 16; j++) f[j] = cp[(size_t)j * S] * s;
        } else {            // d-features (jobs 0/1 only)
            const float* bp = g_xt + (size_t)(256 + 3 * (kg0 - 256)) * S + frow;
            #pragma unroll
            for (int j = 0; j < 16; j++) {
                float e0 = bp[(size_t)(3*j)   * S];
                float e1 = bp[(size_t)(3*j+1) * S];
                float e2 = bp[(size_t)(3*j+2) * S];
                f[j] = e0 * yv[1] + e1 * yv[2] + e2 * yv[3];
            }
        }
    };
    auto storeA = [&](int b, int half, const float* f) {
        uint32_t* ap = sm + b * A_TILE + fm * AS_STRIDE + half * 16 + kwo;
        *(uint4*)(ap)     = make_uint4(pack_h2(f[0], f[1]),   pack_h2(f[2], f[3]),
                                       pack_h2(f[4], f[5]),   pack_h2(f[6], f[7]));
        *(uint4*)(ap + 4) = make_uint4(pack_h2(f[8], f[9]),   pack_h2(f[10], f[11]),
                                       pack_h2(f[12], f[13]), pack_h2(f[14], f[15]));
    };

    float f[16];
    issueW(0, 0);
    load_feat(klo, f);      storeA(0, 0, f);
    load_feat(32 + klo, f); storeA(0, 1, f);

    for (int kt = 0; kt < KT; kt++) {
        const int b = kt & 1;
        asm volatile("cp.async.wait_group 0;" ::: "memory");
        __syncthreads();
        const bool more = (kt + 1 < KT);
        if (more) { issueW(kt + 1, b ^ 1); load_feat((kt + 1) * BK + klo, f); }

        const uint32_t* Ab = sm + b * A_TILE;
        const uint32_t* Wb = sm + OFF_W + b * W_TILE;
        #pragma unroll
        for (int ks = 0; ks < 2; ks++) {
            const int base = ks * 8;
            uint32_t a[2][4];
            #pragma unroll
            for (int mi = 0; mi < 2; mi++) {
                const uint32_t* p = &Ab[(wm * 32 + mi * 16 + qr) * AS_STRIDE + base + qc];
                a[mi][0] = p[0]; a[mi][1] = p[8 * AS_STRIDE];
                a[mi][2] = p[4]; a[mi][3] = p[8 * AS_STRIDE + 4];
            }
            #pragma unroll
            for (int ni = 0; ni < 8; ni++) {
                uint32_t bb[2];
                const uint32_t* q = &Wb[(base + qc) * WS_STRIDE + wn * 64 + ni * 8 + qr];
                bb[0] = q[0]; bb[1] = q[4 * WS_STRIDE];
                mma_f16(acc[0][ni], a[0], bb);
                mma_f16(acc[1][ni], a[1], bb);
            }
        }
        if (more) { storeA(b ^ 1, 0, f); load_feat((kt + 1) * BK + 32 + klo, f); }
        #pragma unroll
        for (int ks = 2; ks < 4; ks++) {
            const int base = ks * 8;
            uint32_t a[2][4];
            #pragma unroll
            for (int mi = 0; mi < 2; mi++) {
                const uint32_t* p = &Ab[(wm * 32 + mi * 16 + qr) * AS_STRIDE + base + qc];
                a[mi][0] = p[0]; a[mi][1] = p[8 * AS_STRIDE];
                a[mi][2] = p[4]; a[mi][3] = p[8 * AS_STRIDE + 4];
            }
            #pragma unroll
            for (int ni = 0; ni < 8; ni++) {
                uint32_t bb[2];
                const uint32_t* q = &Wb[(base + qc) * WS_STRIDE + wn * 64 + ni * 8 + qr];
                bb[0] = q[0]; bb[1] = q[4 * WS_STRIDE];
                mma_f16(acc[0][ni], a[0], bb);
                mma_f16(acc[1][ni], a[1], bb);
            }
        }
        if (more) storeA(b ^ 1, 1, f);
    }

    const float* bias = (const float*)(sm + OFF_BIAS);
    #pragma unroll
    for (int mi = 0; mi < 2; mi++) {
        #pragma unroll
        for (int half = 0; half < 2; half++) {
            int row = row0 + wm * 32 + mi * 16 + qr + half * 8;
            if (row >= B) continue;
            if (!is_z) {
                float* o = out + (size_t)row * 640 + job * 128;
                #pragma unroll
                for (int ni = 0; ni < 8; ni++) {
                    int col = wn * 64 + ni * 8 + qc * 2;
                    *(float2*)(o + col) = make_float2(
                        acc[mi][ni][half * 2]     + bias[col],
                        acc[mi][ni][half * 2 + 1] + bias[col + 1]);
                }
            } else {
                float* o = g_z + (size_t)row * 128;
                #pragma unroll
                for (int ni = 0; ni < 8; ni++) {
                    int col = wn * 64 + ni * 8 + qc * 2;
                    *(float2*)(o + col) = make_float2(acc[mi][ni][half * 2],
                                                      acc[mi][ni][half * 2 + 1]);
                }
            }
        }
    }
}

// ================= phase B: out1 regions (jobs 0..2 = i0) =================
__global__ void __launch_bounds__(NT, 2)
tpr_b(const float* __restrict__ y, float* __restrict__ out, int B, int S)
{
    extern __shared__ uint32_t sm[];
    const uint32_t sb = smem_u32(sm);

    const int i0   = blockIdx.x;
    const int row0 = blockIdx.y * BM;
    const int tid  = threadIdx.x;
    const int wid  = tid >> 5;
    const int lane = tid & 31;
    const int qr = lane >> 2, qc = lane & 3;
    const int wm = wid & 3, wn = wid >> 2;
    const int j1 = (i0 + 1) % 3;
    const int j2 = (i0 + 2) % 3;
    const int KT = 4;
    const uint32_t* wbase = g_wt + 65536;

    const int fm   = tid >> 1;
    const int klo  = (tid & 1) * 16;
    const int kwo  = (tid & 1) * 8;
    const int frow = row0 + fm;
    const bool valid = frow < B;
    float yv[4] = {0.f, 0.f, 0.f, 0.f};
    if (valid) {
        float4 t = *(const float4*)(y + (size_t)frow * 4);
        yv[0] = t.x; yv[1] = t.y; yv[2] = t.z; yv[3] = t.w;
    }

    float acc[2][8][4];
    #pragma unroll
    for (int mi = 0; mi < 2; mi++)
        #pragma unroll
        for (int ni = 0; ni < 8; ni++)
            #pragma unroll
            for (int c = 0; c < 4; c++) acc[mi][ni][c] = 0.f;

    auto issueW = [&](int kt, int b) {
        const uint32_t dbase = sb + (OFF_W + b * W_TILE) * 4;
        const uint32_t* src = wbase + (size_t)(kt * KP) * 128;
        #pragma unroll
        for (int i = 0; i < 4; i++) {
            int idx = tid + i * NT;
            int kw = idx >> 5, c16 = (idx & 31) * 4;
            cp16(dbase + (uint32_t)(kw * WS_STRIDE + c16) * 4, src + kw * 128 + c16);
        }
        asm volatile("cp.async.commit_group;" ::: "memory");
    };

    // A = [x1_i*y0 (k<128) | cr_i (k in 128..256)]
    auto load_feat = [&](int kg0, float* f) {
        if (!valid) {
            #pragma unroll
            for (int j = 0; j < 16; j++) f[j] = 0.f;
        } else if (kg0 < 128) {
            const float* bp = g_xt + (size_t)(256 + 3 * kg0) * S + frow;
            #pragma unroll
            for (int j = 0; j < 16; j++)
                f[j] = bp[(size_t)(3*j + i0) * S] * yv[0];
        } else {
            const float* bp = g_xt + (size_t)(256 + 3 * (kg0 - 128)) * S + frow;
            #pragma unroll
            for (int j = 0; j < 16; j++) {
                float xa = bp[(size_t)(3*j + j1) * S];
                float xb = bp[(size_t)(3*j + j2) * S];
                f[j] = xa * yv[1 + j2] - xb * yv[1 + j1];
            }
        }
    };
    auto storeA = [&](int b, int half, const float* f) {
        uint32_t* ap = sm + b * A_TILE + fm * AS_STRIDE + half * 16 + kwo;
        *(uint4*)(ap)     = make_uint4(pack_h2(f[0], f[1]),   pack_h2(f[2], f[3]),
                                       pack_h2(f[4], f[5]),   pack_h2(f[6], f[7]));
        *(uint4*)(ap + 4) = make_uint4(pack_h2(f[8], f[9]),   pack_h2(f[10], f[11]),
                                       pack_h2(f[12], f[13]), pack_h2(f[14], f[15]));
    };

    float f[16];
    issueW(0, 0);
    load_feat(klo, f);      storeA(0, 0, f);
    load_feat(32 + klo, f); storeA(0, 1, f);

    for (int kt = 0; kt < KT; kt++) {
        const int b = kt & 1;
        asm volatile("cp.async.wait_group 0;" ::: "memory");
        __syncthreads();
        const bool more = (kt + 1 < KT);
        if (more) { issueW(kt + 1, b ^ 1); load_feat((kt + 1) * BK + klo, f); }

        const uint32_t* Ab = sm + b * A_TILE;
        const uint32_t* Wb = sm + OFF_W + b * W_TILE;
        #pragma unroll
        for (int ks = 0; ks < 2; ks++) {
            const int base = ks * 8;
            uint32_t a[2][4];
            #pragma unroll
            for (int mi = 0; mi < 2; mi++) {
                const uint32_t* p = &Ab[(wm * 32 + mi * 16 + qr) * AS_STRIDE + base + qc];
                a[mi][0] = p[0]; a[mi][1] = p[8 * AS_STRIDE];
                a[mi][2] = p[4]; a[mi][3] = p[8 * AS_STRIDE + 4];
            }
            #pragma unroll
            for (int ni = 0; ni < 8; ni++) {
                uint32_t bb[2];
                const uint32_t* q = &Wb[(base + qc) * WS_STRIDE + wn * 64 + ni * 8 + qr];
                bb[0] = q[0]; bb[1] = q[4 * WS_STRIDE];
                mma_f16(acc[0][ni], a[0], bb);
                mma_f16(acc[1][ni], a[1], bb);
            }
        }
        if (more) { storeA(b ^ 1, 0, f); load_feat((kt + 1) * BK + 32 + klo, f); }
        #pragma unroll
        for (int ks = 2; ks < 4; ks++) {
            const int base = ks * 8;
            uint32_t a[2][4];
            #pragma unroll
            for (int mi = 0; mi < 2; mi++) {
                const uint32_t* p = &Ab[(wm * 32 + mi * 16 + qr) * AS_STRIDE + base + qc];
                a[mi][0] = p[0]; a[mi][1] = p[8 * AS_STRIDE];
                a[mi][2] = p[4]; a[mi][3] = p[8 * AS_STRIDE + 4];
            }
            #pragma unroll
            for (int ni = 0; ni < 8; ni++) {
                uint32_t bb[2];
                const uint32_t* q = &Wb[(base + qc) * WS_STRIDE + wn * 64 + ni * 8 + qr];
                bb[0] = q[0]; bb[1] = q[4 * WS_STRIDE];
                mma_f16(acc[0][ni], a[0], bb);
                mma_f16(acc[1][ni], a[1], bb);
            }
        }
        if (more) storeA(b ^ 1, 1, f);
    }

    // epilogue: out1_i = acc + z011s * y1_i  (strided store)
    #pragma unroll
    for (int mi = 0; mi < 2; mi++) {
        #pragma unroll
        for (int half = 0; half < 2; half++) {
            int row = row0 + wm * 32 + mi * 16 + qr + half * 8;
            if (row >= B) continue;
            float yg = y[(size_t)row * 4 + 1 + i0];
            const float* zr = g_z + (size_t)row * 128;
            float* o = out + (size_t)row * 640 + 256 + i0;
            #pragma unroll
            for (int ni = 0; ni < 8; ni++) {
                int col = wn * 64 + ni * 8 + qc * 2;
                float2 z2 = *(const float2*)(zr + col);
                o[col * 3]       = acc[mi][ni][half * 2]     + z2.x * yg;
                o[(col + 1) * 3] = acc[mi][ni][half * 2 + 1] + z2.y * yg;
            }
        }
    }
}

extern "C" void kernel_launch(void* const* d_in, const int* in_sizes, int n_in,
                              void* d_out, int out_size)
{
    const float* x    = (const float*)d_in[0];
    const float* y    = (const float*)d_in[1];
    const float* w000 = (const float*)d_in[2];
    const float* w110 = (const float*)d_in[3];
    const float* w011 = (const float*)d_in[4];
    const float* w101 = (const float*)d_in[5];
    const float* w111 = (const float*)d_in[6];
    const float* b0   = (const float*)d_in[7];
    int B = in_sizes[0] / 640;
    int S = (B + 127) & ~127;
    if (S > MAXS) S = MAXS;

    cudaFuncSetAttribute(tpr_a, cudaFuncAttributeMaxDynamicSharedMemorySize, SMEM_BYTES);
    cudaFuncSetAttribute(tpr_b, cudaFuncAttributeMaxDynamicSharedMemorySize, SMEM_BYTES);

    prep_wt<<<(81920 + 255) / 256, 256>>>(w000, w110, w011, w101, w111);
    {
        dim3 tb(32, 8), tg(640 / 32, S / 32);
        prep_xt<<<tg, tb>>>(x, B, S);
    }

    dim3 grid(3, (B + BM - 1) / BM);
    tpr_a<<<grid, NT, SMEM_BYTES>>>(y, b0, (float*)d_out, B, S);
    tpr_b<<<grid, NT, SMEM_BYTES>>>(y, (float*)d_out, B, S);
}

// round 16
// speedup vs baseline: 1.7608x; 1.0374x over previous
#include <cuda_runtime.h>
#include <cuda_fp16.h>
#include <cstdint>

#define NT 256                 // 8 warps: 4 (m) x 2 (n), warp tile 32x64
#define BM 128
#define BK 64                  // K floats per tile -> 32 half2 words
#define KP 32
#define AS_STRIDE 36           // u32 stride [m][kp]
#define WS_STRIDE 136          // u32 stride [kp][n]
#define A_TILE (BM * AS_STRIDE)
#define W_TILE (KP * WS_STRIDE)
#define OFF_W  (2 * A_TILE)
#define OFF_BIAS (2 * A_TILE + 2 * W_TILE)
#define SMEM_BYTES ((2 * A_TILE + 2 * W_TILE + 128) * 4)   // 72192 B

#define MAXS 150016

// weights (fp16x2, scales folded), u32 layout:
//  [0)      job0: out0 cb0, 192 kp x 128
//  [24576)  job1: out0 cb1, 192 kp x 128
//  [49152)  z011: SQK1*w011, 128 kp x 128
//  [65536)  regions: [SQK1*w101 ; SQK1*IS2*w111], 128 kp x 128
__device__ uint32_t g_wt[81920];
__device__ __half g_xt[640ull * MAXS];     // x transposed, fp16: [c][S]
__device__ float g_z[(size_t)MAXS * 128];  // z011 scratch (SQK1 folded)

__device__ __forceinline__ uint32_t smem_u32(const void* p) {
    uint32_t a;
    asm("{ .reg .u64 t; cvta.to.shared.u64 t, %1; cvt.u32.u64 %0, t; }" : "=r"(a) : "l"(p));
    return a;
}
__device__ __forceinline__ void cp16(uint32_t dst, const void* src) {
    asm volatile("cp.async.ca.shared.global [%0], [%1], 16;" :: "r"(dst), "l"(src));
}
__device__ __forceinline__ uint32_t pack_h2(float lo, float hi) {
    half2 h = __floats2half2_rn(lo, hi);
    return *(uint32_t*)&h;
}
__device__ __forceinline__ void mma_f16(float* d, const uint32_t* a, const uint32_t* b) {
    asm volatile(
        "mma.sync.aligned.m16n8k16.row.col.f32.f16.f16.f32 "
        "{%0,%1,%2,%3}, {%4,%5,%6,%7}, {%8,%9}, {%0,%1,%2,%3};"
        : "+f"(d[0]), "+f"(d[1]), "+f"(d[2]), "+f"(d[3])
        : "r"(a[0]), "r"(a[1]), "r"(a[2]), "r"(a[3]), "r"(b[0]), "r"(b[1]));
}

// ---------------- prep: transpose x -> g_xt (fp16) ----------------
__global__ void prep_xt(const float* __restrict__ x, int B, int S)
{
    __shared__ float t[32][33];
    const int tx = threadIdx.x, ty = threadIdx.y;
    const int c0 = blockIdx.x * 32;
    const int r0 = blockIdx.y * 32;
    #pragma unroll
    for (int i = 0; i < 4; i++) {
        int r = r0 + ty + i * 8;
        t[ty + i * 8][tx] = (r < B) ? x[(size_t)r * 640 + c0 + tx] : 0.0f;
    }
    __syncthreads();
    #pragma unroll
    for (int i = 0; i < 4; i++) {
        int c = c0 + ty + i * 8;
        g_xt[(size_t)c * S + r0 + tx] = __float2half_rn(t[tx][ty + i * 8]);
    }
}

// ---------------- prep: fold scales + fp16 pack ----------------
__global__ void prep_wt(const float* __restrict__ w000, const float* __restrict__ w110,
                        const float* __restrict__ w011, const float* __restrict__ w101,
                        const float* __restrict__ w111)
{
    const float SQK0 = 0.05103103630798288f;
    const float SQK1 = 0.04419417382415922f;
    const float IS3  = 0.57735026918962584f;
    const float IS2  = 0.70710678118654752f;

    int idx = blockIdx.x * 256 + threadIdx.x;
    if (idx >= 81920) return;
    float w2[2];
    if (idx < 49152) {
        int job = idx / 24576, rem = idx % 24576;
        int kp = rem >> 7, n = rem & 127, cb = job;
        #pragma unroll
        for (int h = 0; h < 2; h++) {
            int k = 2 * kp + h;
            w2[h] = (k < 256) ? SQK0 * w000[k * 256 + cb * 128 + n]
                              : SQK0 * IS3 * w110[(k - 256) * 256 + cb * 128 + n];
        }
    } else if (idx < 65536) {
        int rem = idx - 49152;
        int kp = rem >> 7, n = rem & 127;
        #pragma unroll
        for (int h = 0; h < 2; h++)
            w2[h] = SQK1 * w011[(2 * kp + h) * 128 + n];
    } else {
        int rem = idx - 65536;
        int kp = rem >> 7, n = rem & 127;
        #pragma unroll
        for (int h = 0; h < 2; h++) {
            int k = 2 * kp + h;
            w2[h] = (k < 128) ? SQK1 * w101[k * 128 + n]
                              : SQK1 * IS2 * w111[(k - 128) * 128 + n];
        }
    }
    g_wt[idx] = pack_h2(w2[0], w2[1]);
}

// ================= phase A: out0 (jobs 0,1) + z011 (job 2) =================
__global__ void __launch_bounds__(NT, 2)
tpr_a(const float* __restrict__ y, const float* __restrict__ b0,
      float* __restrict__ out, int B, int S)
{
    extern __shared__ uint32_t sm[];
    const uint32_t sb = smem_u32(sm);

    const int job  = blockIdx.x;
    const int row0 = blockIdx.y * BM;
    const int tid  = threadIdx.x;
    const int wid  = tid >> 5;
    const int lane = tid & 31;
    const int qr = lane >> 2, qc = lane & 3;
    const int wm = wid & 3, wn = wid >> 2;

    const bool is_z = (job == 2);
    const int KT = is_z ? 4 : 6;
    const uint32_t* wbase = g_wt + (is_z ? 49152 : job * 24576);

    const int fm   = tid >> 1;
    const int klo  = (tid & 1) * 16;
    const int kwo  = (tid & 1) * 8;
    const int frow = row0 + fm;
    const bool valid = frow < B;
    float yv[4] = {0.f, 0.f, 0.f, 0.f};
    if (valid) {
        float4 t = *(const float4*)(y + (size_t)frow * 4);
        yv[0] = t.x; yv[1] = t.y; yv[2] = t.z; yv[3] = t.w;
    }
    if (!is_z && tid < 128)
        ((float*)(sm + OFF_BIAS))[tid] = b0[job * 128 + tid];

    float acc[2][8][4];
    #pragma unroll
    for (int mi = 0; mi < 2; mi++)
        #pragma unroll
        for (int ni = 0; ni < 8; ni++)
            #pragma unroll
            for (int c = 0; c < 4; c++) acc[mi][ni][c] = 0.f;

    auto issueW = [&](int kt, int b) {
        const uint32_t dbase = sb + (OFF_W + b * W_TILE) * 4;
        const uint32_t* src = wbase + (size_t)(kt * KP) * 128;
        #pragma unroll
        for (int i = 0; i < 4; i++) {
            int idx = tid + i * NT;
            int kw = idx >> 5, c16 = (idx & 31) * 4;
            cp16(dbase + (uint32_t)(kw * WS_STRIDE + c16) * 4, src + kw * 128 + c16);
        }
        asm volatile("cp.async.commit_group;" ::: "memory");
    };

    auto load_feat = [&](int kg0, float* f) {
        if (!valid) {
            #pragma unroll
            for (int j = 0; j < 16; j++) f[j] = 0.f;
        } else if (kg0 < 256) {
            float s = is_z ? 1.0f : yv[0];
            const __half* cp = g_xt + (size_t)kg0 * S + frow;
            #pragma unroll
            for (int j = 0; j < 16; j++)
                f[j] = __half2float(cp[(size_t)j * S]) * s;
        } else {            // d-features (jobs 0/1 only)
            const __half* bp = g_xt + (size_t)(256 + 3 * (kg0 - 256)) * S + frow;
            #pragma unroll
            for (int j = 0; j < 16; j++) {
                float e0 = __half2float(bp[(size_t)(3*j)   * S]);
                float e1 = __half2float(bp[(size_t)(3*j+1) * S]);
                float e2 = __half2float(bp[(size_t)(3*j+2) * S]);
                f[j] = e0 * yv[1] + e1 * yv[2] + e2 * yv[3];
            }
        }
    };
    auto storeA = [&](int b, int half, const float* f) {
        uint32_t* ap = sm + b * A_TILE + fm * AS_STRIDE + half * 16 + kwo;
        *(uint4*)(ap)     = make_uint4(pack_h2(f[0], f[1]),   pack_h2(f[2], f[3]),
                                       pack_h2(f[4], f[5]),   pack_h2(f[6], f[7]));
        *(uint4*)(ap + 4) = make_uint4(pack_h2(f[8], f[9]),   pack_h2(f[10], f[11]),
                                       pack_h2(f[12], f[13]), pack_h2(f[14], f[15]));
    };

    float f[16];
    issueW(0, 0);
    load_feat(klo, f);      storeA(0, 0, f);
    load_feat(32 + klo, f); storeA(0, 1, f);

    for (int kt = 0; kt < KT; kt++) {
        const int b = kt & 1;
        asm volatile("cp.async.wait_group 0;" ::: "memory");
        __syncthreads();
        const bool more = (kt + 1 < KT);
        if (more) { issueW(kt + 1, b ^ 1); load_feat((kt + 1) * BK + klo, f); }

        const uint32_t* Ab = sm + b * A_TILE;
        const uint32_t* Wb = sm + OFF_W + b * W_TILE;
        #pragma unroll
        for (int ks = 0; ks < 2; ks++) {
            const int base = ks * 8;
            uint32_t a[2][4];
            #pragma unroll
            for (int mi = 0; mi < 2; mi++) {
                const uint32_t* p = &Ab[(wm * 32 + mi * 16 + qr) * AS_STRIDE + base + qc];
                a[mi][0] = p[0]; a[mi][1] = p[8 * AS_STRIDE];
                a[mi][2] = p[4]; a[mi][3] = p[8 * AS_STRIDE + 4];
            }
            #pragma unroll
            for (int ni = 0; ni < 8; ni++) {
                uint32_t bb[2];
                const uint32_t* q = &Wb[(base + qc) * WS_STRIDE + wn * 64 + ni * 8 + qr];
                bb[0] = q[0]; bb[1] = q[4 * WS_STRIDE];
                mma_f16(acc[0][ni], a[0], bb);
                mma_f16(acc[1][ni], a[1], bb);
            }
        }
        if (more) { storeA(b ^ 1, 0, f); load_feat((kt + 1) * BK + 32 + klo, f); }
        #pragma unroll
        for (int ks = 2; ks < 4; ks++) {
            const int base = ks * 8;
            uint32_t a[2][4];
            #pragma unroll
            for (int mi = 0; mi < 2; mi++) {
                const uint32_t* p = &Ab[(wm * 32 + mi * 16 + qr) * AS_STRIDE + base + qc];
                a[mi][0] = p[0]; a[mi][1] = p[8 * AS_STRIDE];
                a[mi][2] = p[4]; a[mi][3] = p[8 * AS_STRIDE + 4];
            }
            #pragma unroll
            for (int ni = 0; ni < 8; ni++) {
                uint32_t bb[2];
                const uint32_t* q = &Wb[(base + qc) * WS_STRIDE + wn * 64 + ni * 8 + qr];
                bb[0] = q[0]; bb[1] = q[4 * WS_STRIDE];
                mma_f16(acc[0][ni], a[0], bb);
                mma_f16(acc[1][ni], a[1], bb);
            }
        }
        if (more) storeA(b ^ 1, 1, f);
    }

    const float* bias = (const float*)(sm + OFF_BIAS);
    #pragma unroll
    for (int mi = 0; mi < 2; mi++) {
        #pragma unroll
        for (int half = 0; half < 2; half++) {
            int row = row0 + wm * 32 + mi * 16 + qr + half * 8;
            if (row >= B) continue;
            if (!is_z) {
                float* o = out + (size_t)row * 640 + job * 128;
                #pragma unroll
                for (int ni = 0; ni < 8; ni++) {
                    int col = wn * 64 + ni * 8 + qc * 2;
                    *(float2*)(o + col) = make_float2(
                        acc[mi][ni][half * 2]     + bias[col],
                        acc[mi][ni][half * 2 + 1] + bias[col + 1]);
                }
            } else {
                float* o = g_z + (size_t)row * 128;
                #pragma unroll
                for (int ni = 0; ni < 8; ni++) {
                    int col = wn * 64 + ni * 8 + qc * 2;
                    *(float2*)(o + col) = make_float2(acc[mi][ni][half * 2],
                                                      acc[mi][ni][half * 2 + 1]);
                }
            }
        }
    }
}

// ================= phase B: out1 regions (jobs 0..2 = i0) =================
__global__ void __launch_bounds__(NT, 2)
tpr_b(const float* __restrict__ y, float* __restrict__ out, int B, int S)
{
    extern __shared__ uint32_t sm[];
    const uint32_t sb = smem_u32(sm);

    const int i0   = blockIdx.x;
    const int row0 = blockIdx.y * BM;
    const int tid  = threadIdx.x;
    const int wid  = tid >> 5;
    const int lane = tid & 31;
    const int qr = lane >> 2, qc = lane & 3;
    const int wm = wid & 3, wn = wid >> 2;
    const int j1 = (i0 + 1) % 3;
    const int j2 = (i0 + 2) % 3;
    const int KT = 4;
    const uint32_t* wbase = g_wt + 65536;

    const int fm   = tid >> 1;
    const int klo  = (tid & 1) * 16;
    const int kwo  = (tid & 1) * 8;
    const int frow = row0 + fm;
    const bool valid = frow < B;
    float yv[4] = {0.f, 0.f, 0.f, 0.f};
    if (valid) {
        float4 t = *(const float4*)(y + (size_t)frow * 4);
        yv[0] = t.x; yv[1] = t.y; yv[2] = t.z; yv[3] = t.w;
    }

    float acc[2][8][4];
    #pragma unroll
    for (int mi = 0; mi < 2; mi++)
        #pragma unroll
        for (int ni = 0; ni < 8; ni++)
            #pragma unroll
            for (int c = 0; c < 4; c++) acc[mi][ni][c] = 0.f;

    auto issueW = [&](int kt, int b) {
        const uint32_t dbase = sb + (OFF_W + b * W_TILE) * 4;
        const uint32_t* src = wbase + (size_t)(kt * KP) * 128;
        #pragma unroll
        for (int i = 0; i < 4; i++) {
            int idx = tid + i * NT;
            int kw = idx >> 5, c16 = (idx & 31) * 4;
            cp16(dbase + (uint32_t)(kw * WS_STRIDE + c16) * 4, src + kw * 128 + c16);
        }
        asm volatile("cp.async.commit_group;" ::: "memory");
    };

    // A = [x1_i*y0 (k<128) | cr_i (k in 128..256)]
    auto load_feat = [&](int kg0, float* f) {
        if (!valid) {
            #pragma unroll
            for (int j = 0; j < 16; j++) f[j] = 0.f;
        } else if (kg0 < 128) {
            const __half* bp = g_xt + (size_t)(256 + 3 * kg0) * S + frow;
            #pragma unroll
            for (int j = 0; j < 16; j++)
                f[j] = __half2float(bp[(size_t)(3*j + i0) * S]) * yv[0];
        } else {
            const __half* bp = g_xt + (size_t)(256 + 3 * (kg0 - 128)) * S + frow;
            #pragma unroll
            for (int j = 0; j < 16; j++) {
                float xa = __half2float(bp[(size_t)(3*j + j1) * S]);
                float xb = __half2float(bp[(size_t)(3*j + j2) * S]);
                f[j] = xa * yv[1 + j2] - xb * yv[1 + j1];
            }
        }
    };
    auto storeA = [&](int b, int half, const float* f) {
        uint32_t* ap = sm + b * A_TILE + fm * AS_STRIDE + half * 16 + kwo;
        *(uint4*)(ap)     = make_uint4(pack_h2(f[0], f[1]),   pack_h2(f[2], f[3]),
                                       pack_h2(f[4], f[5]),   pack_h2(f[6], f[7]));
        *(uint4*)(ap + 4) = make_uint4(pack_h2(f[8], f[9]),   pack_h2(f[10], f[11]),
                                       pack_h2(f[12], f[13]), pack_h2(f[14], f[15]));
    };

    float f[16];
    issueW(0, 0);
    load_feat(klo, f);      storeA(0, 0, f);
    load_feat(32 + klo, f); storeA(0, 1, f);

    for (int kt = 0; kt < KT; kt++) {
        const int b = kt & 1;
        asm volatile("cp.async.wait_group 0;" ::: "memory");
        __syncthreads();
        const bool more = (kt + 1 < KT);
        if (more) { issueW(kt + 1, b ^ 1); load_feat((kt + 1) * BK + klo, f); }

        const uint32_t* Ab = sm + b * A_TILE;
        const uint32_t* Wb = sm + OFF_W + b * W_TILE;
        #pragma unroll
        for (int ks = 0; ks < 2; ks++) {
            const int base = ks * 8;
            uint32_t a[2][4];
            #pragma unroll
            for (int mi = 0; mi < 2; mi++) {
                const uint32_t* p = &Ab[(wm * 32 + mi * 16 + qr) * AS_STRIDE + base + qc];
                a[mi][0] = p[0]; a[mi][1] = p[8 * AS_STRIDE];
                a[mi][2] = p[4]; a[mi][3] = p[8 * AS_STRIDE + 4];
            }
            #pragma unroll
            for (int ni = 0; ni < 8; ni++) {
                uint32_t bb[2];
                const uint32_t* q = &Wb[(base + qc) * WS_STRIDE + wn * 64 + ni * 8 + qr];
                bb[0] = q[0]; bb[1] = q[4 * WS_STRIDE];
                mma_f16(acc[0][ni], a[0], bb);
                mma_f16(acc[1][ni], a[1], bb);
            }
        }
        if (more) { storeA(b ^ 1, 0, f); load_feat((kt + 1) * BK + 32 + klo, f); }
        #pragma unroll
        for (int ks = 2; ks < 4; ks++) {
            const int base = ks * 8;
            uint32_t a[2][4];
            #pragma unroll
            for (int mi = 0; mi < 2; mi++) {
                const uint32_t* p = &Ab[(wm * 32 + mi * 16 + qr) * AS_STRIDE + base + qc];
                a[mi][0] = p[0]; a[mi][1] = p[8 * AS_STRIDE];
                a[mi][2] = p[4]; a[mi][3] = p[8 * AS_STRIDE + 4];
            }
            #pragma unroll
            for (int ni = 0; ni < 8; ni++) {
                uint32_t bb[2];
                const uint32_t* q = &Wb[(base + qc) * WS_STRIDE + wn * 64 + ni * 8 + qr];
                bb[0] = q[0]; bb[1] = q[4 * WS_STRIDE];
                mma_f16(acc[0][ni], a[0], bb);
                mma_f16(acc[1][ni], a[1], bb);
            }
        }
        if (more) storeA(b ^ 1, 1, f);
    }

    // epilogue: out1_i = acc + z011s * y1_i  (strided store)
    #pragma unroll
    for (int mi = 0; mi < 2; mi++) {
        #pragma unroll
        for (int half = 0; half < 2; half++) {
            int row = row0 + wm * 32 + mi * 16 + qr + half * 8;
            if (row >= B) continue;
            float yg = y[(size_t)row * 4 + 1 + i0];
            const float* zr = g_z + (size_t)row * 128;
            float* o = out + (size_t)row * 640 + 256 + i0;
            #pragma unroll
            for (int ni = 0; ni < 8; ni++) {
                int col = wn * 64 + ni * 8 + qc * 2;
                float2 z2 = *(const float2*)(zr + col);
                o[col * 3]       = acc[mi][ni][half * 2]     + z2.x * yg;
                o[(col + 1) * 3] = acc[mi][ni][half * 2 + 1] + z2.y * yg;
            }
        }
    }
}

extern "C" void kernel_launch(void* const* d_in, const int* in_sizes, int n_in,
                              void* d_out, int out_size)
{
    const float* x    = (const float*)d_in[0];
    const float* y    = (const float*)d_in[1];
    const float* w000 = (const float*)d_in[2];
    const float* w110 = (const float*)d_in[3];
    const float* w011 = (const float*)d_in[4];
    const float* w101 = (const float*)d_in[5];
    const float* w111 = (const float*)d_in[6];
    const float* b0   = (const float*)d_in[7];
    int B = in_sizes[0] / 640;
    int S = (B + 127) & ~127;
    if (S > MAXS) S = MAXS;

    cudaFuncSetAttribute(tpr_a, cudaFuncAttributeMaxDynamicSharedMemorySize, SMEM_BYTES);
    cudaFuncSetAttribute(tpr_b, cudaFuncAttributeMaxDynamicSharedMemorySize, SMEM_BYTES);

    prep_wt<<<(81920 + 255) / 256, 256>>>(w000, w110, w011, w101, w111);
    {
        dim3 tb(32, 8), tg(640 / 32, S / 32);
        prep_xt<<<tg, tb>>>(x, B, S);
    }

    dim3 grid(3, (B + BM - 1) / BM);
    tpr_a<<<grid, NT, SMEM_BYTES>>>(y, b0, (float*)d_out, B, S);
    tpr_b<<<grid, NT, SMEM_BYTES>>>(y, (float*)d_out, B, S);
}

// round 17
// speedup vs baseline: 1.9120x; 1.0859x over previous
#include <cuda_runtime.h>
#include <cuda_fp16.h>
#include <cstdint>

#define NT 256                 // 8 warps: 4 (m) x 2 (n), warp tile 32x64
#define BM 128
#define BK 64                  // K floats per tile -> 32 half2 words
#define KP 32
#define AS_STRIDE 36           // u32 stride [m][kp]
#define WS_STRIDE 136          // u32 stride [kp][n]
#define A_TILE (BM * AS_STRIDE)
#define W_TILE (KP * WS_STRIDE)
#define OFF_W  (2 * A_TILE)
#define OFF_BIAS (2 * A_TILE + 2 * W_TILE)
#define SMEM_BYTES ((2 * A_TILE + 2 * W_TILE + 128) * 4)   // 72192 B

#define MAXS 150016

// weights (fp16x2, scales folded), u32 layout:
//  [0)      job0: out0 cb0, 192 kp x 128
//  [24576)  job1: out0 cb1, 192 kp x 128
//  [49152)  z011: SQK1*w011, 128 kp x 128
//  [65536)  regions: [SQK1*w101 ; SQK1*IS2*w111], 128 kp x 128
__device__ uint32_t g_wt[81920];
// x repacked as half2 k-pairs, column-major over rows:
__device__ uint32_t g_x0p[128ull * MAXS];        // [kp][S], pairs (x[2kp], x[2kp+1])
__device__ uint32_t g_x1p[192ull * MAXS];        // [c*64+up][S], pairs (x1[2up,c], x1[2up+1,c])
__device__ uint32_t g_z[(size_t)MAXS * 64];      // z011 scratch, half2 pairs [r][64]

__device__ __forceinline__ uint32_t smem_u32(const void* p) {
    uint32_t a;
    asm("{ .reg .u64 t; cvta.to.shared.u64 t, %1; cvt.u32.u64 %0, t; }" : "=r"(a) : "l"(p));
    return a;
}
__device__ __forceinline__ void cp16(uint32_t dst, const void* src) {
    asm volatile("cp.async.ca.shared.global [%0], [%1], 16;" :: "r"(dst), "l"(src));
}
__device__ __forceinline__ uint32_t pack_h2(float lo, float hi) {
    half2 h = __floats2half2_rn(lo, hi);
    return *(uint32_t*)&h;
}
__device__ __forceinline__ half2 u2h(uint32_t u) { return *(half2*)&u; }
__device__ __forceinline__ uint32_t h2u(half2 h) { return *(uint32_t*)&h; }
__device__ __forceinline__ void mma_f16(float* d, const uint32_t* a, const uint32_t* b) {
    asm volatile(
        "mma.sync.aligned.m16n8k16.row.col.f32.f16.f16.f32 "
        "{%0,%1,%2,%3}, {%4,%5,%6,%7}, {%8,%9}, {%0,%1,%2,%3};"
        : "+f"(d[0]), "+f"(d[1]), "+f"(d[2]), "+f"(d[3])
        : "r"(a[0]), "r"(a[1]), "r"(a[2]), "r"(a[3]), "r"(b[0]), "r"(b[1]));
}

// ---------------- prep: pack x -> g_x0p / g_x1p (half2 k-pairs) ----------------
__global__ void __launch_bounds__(256, 1)
prep_x(const float* __restrict__ x, int B, int S)
{
    extern __shared__ float sxt[];         // [640][33]: sxt[c*33 + r]
    const int tid  = threadIdx.x;
    const int wid  = tid >> 5;
    const int lane = tid & 31;
    const int r0   = blockIdx.x * 32;

    #pragma unroll
    for (int i = 0; i < 80; i++) {
        int idx = tid + i * 256;
        int r = idx / 640, c = idx % 640;
        float v = (r0 + r < B) ? x[(size_t)(r0 + r) * 640 + c] : 0.0f;
        sxt[c * 33 + r] = v;
    }
    __syncthreads();

    for (int g = wid; g < 320; g += 8) {
        uint32_t val;
        size_t dst;
        if (g < 128) {
            val = pack_h2(sxt[(2 * g) * 33 + lane], sxt[(2 * g + 1) * 33 + lane]);
            dst = (size_t)g * S + r0 + lane;
            g_x0p[dst] = val;
        } else {
            int t  = g - 128;
            int c  = t >> 6;          // component 0..2
            int up = t & 63;          // u-pair
            int ca = 256 + 6 * up + c;
            val = pack_h2(sxt[ca * 33 + lane], sxt[(ca + 3) * 33 + lane]);
            dst = (size_t)t * S + r0 + lane;
            g_x1p[dst] = val;
        }
    }
}

// ---------------- prep: fold scales + fp16 pack weights ----------------
__global__ void prep_wt(const float* __restrict__ w000, const float* __restrict__ w110,
                        const float* __restrict__ w011, const float* __restrict__ w101,
                        const float* __restrict__ w111)
{
    const float SQK0 = 0.05103103630798288f;
    const float SQK1 = 0.04419417382415922f;
    const float IS3  = 0.57735026918962584f;
    const float IS2  = 0.70710678118654752f;

    int idx = blockIdx.x * 256 + threadIdx.x;
    if (idx >= 81920) return;
    float w2[2];
    if (idx < 49152) {
        int job = idx / 24576, rem = idx % 24576;
        int kp = rem >> 7, n = rem & 127, cb = job;
        #pragma unroll
        for (int h = 0; h < 2; h++) {
            int k = 2 * kp + h;
            w2[h] = (k < 256) ? SQK0 * w000[k * 256 + cb * 128 + n]
                              : SQK0 * IS3 * w110[(k - 256) * 256 + cb * 128 + n];
        }
    } else if (idx < 65536) {
        int rem = idx - 49152;
        int kp = rem >> 7, n = rem & 127;
        #pragma unroll
        for (int h = 0; h < 2; h++)
            w2[h] = SQK1 * w011[(2 * kp + h) * 128 + n];
    } else {
        int rem = idx - 65536;
        int kp = rem >> 7, n = rem & 127;
        #pragma unroll
        for (int h = 0; h < 2; h++) {
            int k = 2 * kp + h;
            w2[h] = (k < 128) ? SQK1 * w101[k * 128 + n]
                              : SQK1 * IS2 * w111[(k - 128) * 128 + n];
        }
    }
    g_wt[idx] = pack_h2(w2[0], w2[1]);
}

// ================= phase A: out0 (jobs 0,1) + z011 (job 2) =================
__global__ void __launch_bounds__(NT, 2)
tpr_a(const float* __restrict__ y, const float* __restrict__ b0,
      float* __restrict__ out, int B, int S)
{
    extern __shared__ uint32_t sm[];
    const uint32_t sb = smem_u32(sm);

    const int job  = blockIdx.x;
    const int row0 = blockIdx.y * BM;
    const int tid  = threadIdx.x;
    const int wid  = tid >> 5;
    const int lane = tid & 31;
    const int qr = lane >> 2, qc = lane & 3;
    const int wm = wid & 3, wn = wid >> 2;

    const bool is_z = (job == 2);
    const int KT = is_z ? 4 : 6;
    const uint32_t* wbase = g_wt + (is_z ? 49152 : job * 24576);

    const int fm   = tid >> 1;
    const int klo  = (tid & 1) * 16;
    const int kwo  = (tid & 1) * 8;
    const int frow = row0 + fm;
    float yv[4] = {0.f, 0.f, 0.f, 0.f};
    if (frow < B) {
        float4 t = *(const float4*)(y + (size_t)frow * 4);
        yv[0] = t.x; yv[1] = t.y; yv[2] = t.z; yv[3] = t.w;
    }
    const half2 y0h2 = __float2half2_rn(yv[0]);
    const half2 y1h2 = __float2half2_rn(yv[1]);
    const half2 y2h2 = __float2half2_rn(yv[2]);
    const half2 y3h2 = __float2half2_rn(yv[3]);
    if (!is_z && tid < 128)
        ((float*)(sm + OFF_BIAS))[tid] = b0[job * 128 + tid];

    float acc[2][8][4];
    #pragma unroll
    for (int mi = 0; mi < 2; mi++)
        #pragma unroll
        for (int ni = 0; ni < 8; ni++)
            #pragma unroll
            for (int c = 0; c < 4; c++) acc[mi][ni][c] = 0.f;

    auto issueW = [&](int kt, int b) {
        const uint32_t dbase = sb + (OFF_W + b * W_TILE) * 4;
        const uint32_t* src = wbase + (size_t)(kt * KP) * 128;
        #pragma unroll
        for (int i = 0; i < 4; i++) {
            int idx = tid + i * NT;
            int kw = idx >> 5, c16 = (idx & 31) * 4;
            cp16(dbase + (uint32_t)(kw * WS_STRIDE + c16) * 4, src + kw * 128 + c16);
        }
        asm volatile("cp.async.commit_group;" ::: "memory");
    };

    // 8 packed k-pairs at absolute k offset kg0 (multiple of 16)
    auto load_feat = [&](int kg0, uint32_t* u) {
        if (kg0 < 256) {
            const uint32_t* p = g_x0p + (size_t)(kg0 >> 1) * S + frow;
            if (is_z) {
                #pragma unroll
                for (int j = 0; j < 8; j++) u[j] = p[(size_t)j * S];
            } else {
                #pragma unroll
                for (int j = 0; j < 8; j++)
                    u[j] = h2u(__hmul2(u2h(p[(size_t)j * S]), y0h2));
            }
        } else {            // d-features (jobs 0/1 only)
            int up0 = (kg0 - 256) >> 1;
            const uint32_t* pa = g_x1p + (size_t)up0 * S + frow;
            const uint32_t* pb = pa + (size_t)64 * S;
            const uint32_t* pc = pb + (size_t)64 * S;
            #pragma unroll
            for (int j = 0; j < 8; j++) {
                half2 a = u2h(pa[(size_t)j * S]);
                half2 b = u2h(pb[(size_t)j * S]);
                half2 c = u2h(pc[(size_t)j * S]);
                u[j] = h2u(__hfma2(c, y3h2, __hfma2(b, y2h2, __hmul2(a, y1h2))));
            }
        }
    };
    auto storeA = [&](int b, int half, const uint32_t* u) {
        uint32_t* ap = sm + b * A_TILE + fm * AS_STRIDE + half * 16 + kwo;
        *(uint4*)(ap)     = make_uint4(u[0], u[1], u[2], u[3]);
        *(uint4*)(ap + 4) = make_uint4(u[4], u[5], u[6], u[7]);
    };

    uint32_t f[8];
    issueW(0, 0);
    load_feat(klo, f);      storeA(0, 0, f);
    load_feat(32 + klo, f); storeA(0, 1, f);

    for (int kt = 0; kt < KT; kt++) {
        const int b = kt & 1;
        asm volatile("cp.async.wait_group 0;" ::: "memory");
        __syncthreads();
        const bool more = (kt + 1 < KT);
        if (more) { issueW(kt + 1, b ^ 1); load_feat((kt + 1) * BK + klo, f); }

        const uint32_t* Ab = sm + b * A_TILE;
        const uint32_t* Wb = sm + OFF_W + b * W_TILE;
        #pragma unroll
        for (int ks = 0; ks < 2; ks++) {
            const int base = ks * 8;
            uint32_t a[2][4];
            #pragma unroll
            for (int mi = 0; mi < 2; mi++) {
                const uint32_t* p = &Ab[(wm * 32 + mi * 16 + qr) * AS_STRIDE + base + qc];
                a[mi][0] = p[0]; a[mi][1] = p[8 * AS_STRIDE];
                a[mi][2] = p[4]; a[mi][3] = p[8 * AS_STRIDE + 4];
            }
            #pragma unroll
            for (int ni = 0; ni < 8; ni++) {
                uint32_t bb[2];
                const uint32_t* q = &Wb[(base + qc) * WS_STRIDE + wn * 64 + ni * 8 + qr];
                bb[0] = q[0]; bb[1] = q[4 * WS_STRIDE];
                mma_f16(acc[0][ni], a[0], bb);
                mma_f16(acc[1][ni], a[1], bb);
            }
        }
        if (more) { storeA(b ^ 1, 0, f); load_feat((kt + 1) * BK + 32 + klo, f); }
        #pragma unroll
        for (int ks = 2; ks < 4; ks++) {
            const int base = ks * 8;
            uint32_t a[2][4];
            #pragma unroll
            for (int mi = 0; mi < 2; mi++) {
                const uint32_t* p = &Ab[(wm * 32 + mi * 16 + qr) * AS_STRIDE + base + qc];
                a[mi][0] = p[0]; a[mi][1] = p[8 * AS_STRIDE];
                a[mi][2] = p[4]; a[mi][3] = p[8 * AS_STRIDE + 4];
            }
            #pragma unroll
            for (int ni = 0; ni < 8; ni++) {
                uint32_t bb[2];
                const uint32_t* q = &Wb[(base + qc) * WS_STRIDE + wn * 64 + ni * 8 + qr];
                bb[0] = q[0]; bb[1] = q[4 * WS_STRIDE];
                mma_f16(acc[0][ni], a[0], bb);
                mma_f16(acc[1][ni], a[1], bb);
            }
        }
        if (more) storeA(b ^ 1, 1, f);
    }

    const float* bias = (const float*)(sm + OFF_BIAS);
    #pragma unroll
    for (int mi = 0; mi < 2; mi++) {
        #pragma unroll
        for (int half = 0; half < 2; half++) {
            int row = row0 + wm * 32 + mi * 16 + qr + half * 8;
            if (row >= B) continue;
            if (!is_z) {
                float* o = out + (size_t)row * 640 + job * 128;
                #pragma unroll
                for (int ni = 0; ni < 8; ni++) {
                    int col = wn * 64 + ni * 8 + qc * 2;
                    *(float2*)(o + col) = make_float2(
                        acc[mi][ni][half * 2]     + bias[col],
                        acc[mi][ni][half * 2 + 1] + bias[col + 1]);
                }
            } else {
                uint32_t* o = g_z + (size_t)row * 64;
                #pragma unroll
                for (int ni = 0; ni < 8; ni++) {
                    int col = wn * 64 + ni * 8 + qc * 2;
                    o[col >> 1] = pack_h2(acc[mi][ni][half * 2],
                                          acc[mi][ni][half * 2 + 1]);
                }
            }
        }
    }
}

// ================= phase B: out1 regions (jobs 0..2 = i0) =================
__global__ void __launch_bounds__(NT, 2)
tpr_b(const float* __restrict__ y, float* __restrict__ out, int B, int S)
{
    extern __shared__ uint32_t sm[];
    const uint32_t sb = smem_u32(sm);

    const int i0   = blockIdx.x;
    const int row0 = blockIdx.y * BM;
    const int tid  = threadIdx.x;
    const int wid  = tid >> 5;
    const int lane = tid & 31;
    const int qr = lane >> 2, qc = lane & 3;
    const int wm = wid & 3, wn = wid >> 2;
    const int j1 = (i0 + 1) % 3;
    const int j2 = (i0 + 2) % 3;
    const int KT = 4;
    const uint32_t* wbase = g_wt + 65536;

    const int fm   = tid >> 1;
    const int klo  = (tid & 1) * 16;
    const int kwo  = (tid & 1) * 8;
    const int frow = row0 + fm;
    float yv[4] = {0.f, 0.f, 0.f, 0.f};
    if (frow < B) {
        float4 t = *(const float4*)(y + (size_t)frow * 4);
        yv[0] = t.x; yv[1] = t.y; yv[2] = t.z; yv[3] = t.w;
    }
    const half2 y0h2   = __float2half2_rn(yv[0]);
    const half2 yj2h2  = __float2half2_rn(yv[1 + j2]);
    const half2 nyj1h2 = __float2half2_rn(-yv[1 + j1]);

    float acc[2][8][4];
    #pragma unroll
    for (int mi = 0; mi < 2; mi++)
        #pragma unroll
        for (int ni = 0; ni < 8; ni++)
            #pragma unroll
            for (int c = 0; c < 4; c++) acc[mi][ni][c] = 0.f;

    auto issueW = [&](int kt, int b) {
        const uint32_t dbase = sb + (OFF_W + b * W_TILE) * 4;
        const uint32_t* src = wbase + (size_t)(kt * KP) * 128;
        #pragma unroll
        for (int i = 0; i < 4; i++) {
            int idx = tid + i * NT;
            int kw = idx >> 5, c16 = (idx & 31) * 4;
            cp16(dbase + (uint32_t)(kw * WS_STRIDE + c16) * 4, src + kw * 128 + c16);
        }
        asm volatile("cp.async.commit_group;" ::: "memory");
    };

    // A = [x1_i*y0 (k<128) | cr_i (k in 128..256)], packed pairs
    auto load_feat = [&](int kg0, uint32_t* u) {
        if (kg0 < 128) {
            const uint32_t* p = g_x1p + ((size_t)i0 * 64 + (kg0 >> 1)) * S + frow;
            #pragma unroll
            for (int j = 0; j < 8; j++)
                u[j] = h2u(__hmul2(u2h(p[(size_t)j * S]), y0h2));
        } else {
            int up0 = (kg0 - 128) >> 1;
            const uint32_t* pa = g_x1p + ((size_t)j1 * 64 + up0) * S + frow;
            const uint32_t* pb = g_x1p + ((size_t)j2 * 64 + up0) * S + frow;
            #pragma unroll
            for (int j = 0; j < 8; j++) {
                half2 a = u2h(pa[(size_t)j * S]);
                half2 b = u2h(pb[(size_t)j * S]);
                u[j] = h2u(__hfma2(a, yj2h2, __hmul2(b, nyj1h2)));
            }
        }
    };
    auto storeA = [&](int b, int half, const uint32_t* u) {
        uint32_t* ap = sm + b * A_TILE + fm * AS_STRIDE + half * 16 + kwo;
        *(uint4*)(ap)     = make_uint4(u[0], u[1], u[2], u[3]);
        *(uint4*)(ap + 4) = make_uint4(u[4], u[5], u[6], u[7]);
    };

    uint32_t f[8];
    issueW(0, 0);
    load_feat(klo, f);      storeA(0, 0, f);
    load_feat(32 + klo, f); storeA(0, 1, f);

    for (int kt = 0; kt < KT; kt++) {
        const int b = kt & 1;
        asm volatile("cp.async.wait_group 0;" ::: "memory");
        __syncthreads();
        const bool more = (kt + 1 < KT);
        if (more) { issueW(kt + 1, b ^ 1); load_feat((kt + 1) * BK + klo, f); }

        const uint32_t* Ab = sm + b * A_TILE;
        const uint32_t* Wb = sm + OFF_W + b * W_TILE;
        #pragma unroll
        for (int ks = 0; ks < 2; ks++) {
            const int base = ks * 8;
            uint32_t a[2][4];
            #pragma unroll
            for (int mi = 0; mi < 2; mi++) {
                const uint32_t* p = &Ab[(wm * 32 + mi * 16 + qr) * AS_STRIDE + base + qc];
                a[mi][0] = p[0]; a[mi][1] = p[8 * AS_STRIDE];
                a[mi][2] = p[4]; a[mi][3] = p[8 * AS_STRIDE + 4];
            }
            #pragma unroll
            for (int ni = 0; ni < 8; ni++) {
                uint32_t bb[2];
                const uint32_t* q = &Wb[(base + qc) * WS_STRIDE + wn * 64 + ni * 8 + qr];
                bb[0] = q[0]; bb[1] = q[4 * WS_STRIDE];
                mma_f16(acc[0][ni], a[0], bb);
                mma_f16(acc[1][ni], a[1], bb);
            }
        }
        if (more) { storeA(b ^ 1, 0, f); load_feat((kt + 1) * BK + 32 + klo, f); }
        #pragma unroll
        for (int ks = 2; ks < 4; ks++) {
            const int base = ks * 8;
            uint32_t a[2][4];
            #pragma unroll
            for (int mi = 0; mi < 2; mi++) {
                const uint32_t* p = &Ab[(wm * 32 + mi * 16 + qr) * AS_STRIDE + base + qc];
                a[mi][0] = p[0]; a[mi][1] = p[8 * AS_STRIDE];
                a[mi][2] = p[4]; a[mi][3] = p[8 * AS_STRIDE + 4];
            }
            #pragma unroll
            for (int ni = 0; ni < 8; ni++) {
                uint32_t bb[2];
                const uint32_t* q = &Wb[(base + qc) * WS_STRIDE + wn * 64 + ni * 8 + qr];
                bb[0] = q[0]; bb[1] = q[4 * WS_STRIDE];
                mma_f16(acc[0][ni], a[0], bb);
                mma_f16(acc[1][ni], a[1], bb);
            }
        }
        if (more) storeA(b ^ 1, 1, f);
    }

    // epilogue: out1_i = acc + z011 * y1_i  (strided store)
    #pragma unroll
    for (int mi = 0; mi < 2; mi++) {
        #pragma unroll
        for (int half = 0; half < 2; half++) {
            int row = row0 + wm * 32 + mi * 16 + qr + half * 8;
            if (row >= B) continue;
            float yg = y[(size_t)row * 4 + 1 + i0];
            const uint32_t* zr = g_z + (size_t)row * 64;
            float* o = out + (size_t)row * 640 + 256 + i0;
            #pragma unroll
            for (int ni = 0; ni < 8; ni++) {
                int col = wn * 64 + ni * 8 + qc * 2;
                float2 z2 = __half22float2(u2h(zr[col >> 1]));
                o[col * 3]       = acc[mi][ni][half * 2]     + z2.x * yg;
                o[(col + 1) * 3] = acc[mi][ni][half * 2 + 1] + z2.y * yg;
            }
        }
    }
}

extern "C" void kernel_launch(void* const* d_in, const int* in_sizes, int n_in,
                              void* d_out, int out_size)
{
    const float* x    = (const float*)d_in[0];
    const float* y    = (const float*)d_in[1];
    const float* w000 = (const float*)d_in[2];
    const float* w110 = (const float*)d_in[3];
    const float* w011 = (const float*)d_in[4];
    const float* w101 = (const float*)d_in[5];
    const float* w111 = (const float*)d_in[6];
    const float* b0   = (const float*)d_in[7];
    int B = in_sizes[0] / 640;
    int S = (B + 127) & ~127;
    if (S > MAXS) S = MAXS;

    const int PX_SMEM = 640 * 33 * 4;   // 84480 B
    cudaFuncSetAttribute(prep_x, cudaFuncAttributeMaxDynamicSharedMemorySize, PX_SMEM);
    cudaFuncSetAttribute(tpr_a, cudaFuncAttributeMaxDynamicSharedMemorySize, SMEM_BYTES);
    cudaFuncSetAttribute(tpr_b, cudaFuncAttributeMaxDynamicSharedMemorySize, SMEM_BYTES);

    prep_wt<<<(81920 + 255) / 256, 256>>>(w000, w110, w011, w101, w111);
    prep_x<<<S / 32, 256, PX_SMEM>>>(x, B, S);

    dim3 grid(3, (B + BM - 1) / BM);
    tpr_a<<<grid, NT, SMEM_BYTES>>>(y, b0, (float*)d_out, B, S);
    tpr_b<<<grid, NT, SMEM_BYTES>>>(y, (float*)d_out, B, S);
}